// round 7
// baseline (speedup 1.0000x reference)
#include <cuda_runtime.h>
#include <cuda_bf16.h>
#include <mma.h>
#include <cstdint>

using namespace nvcuda;

#define D        128
#define NREL     16
#define NBASES   8
#define TILE     64                                // rows per tile
#define MAXE     600000
#define NTILES   ((MAXE / TILE) + NREL + 2)        // 9393 edge-tile capacity
#define SORT_CAP (NTILES * TILE)                   // 601152

// ---- smem layout (bf16 tiles, row stride 136 elems = 272B) ----
#define LDA      136
#define ROWB     (LDA * 2)          // 272 bytes per row
#define XTILE_B  (TILE * ROWB)      // 17408 bytes (64-row X tile)
#define WTILE_B  (D * ROWB)         // 34816 bytes (128-row W tile)
#define XH_OFF   0
#define XL_OFF   XTILE_B
#define WH_OFF   (2 * XTILE_B)
#define WL_OFF   (2 * XTILE_B + WTILE_B)
#define GEMM_SMEM (2 * XTILE_B + 2 * WTILE_B)      // 104448
#define OLD      132                // f32 out-tile row stride; 64*132*4 <= 2*XTILE_B

// -------- device scratch --------
__device__ __align__(16) __nv_bfloat16 g_Wh[NREL * D * D];   // [r][o][i] bf16 hi
__device__ __align__(16) __nv_bfloat16 g_Wl[NREL * D * D];   // [r][o][i] bf16 lo
__device__ __align__(16) __nv_bfloat16 g_Wsh[D * D];         // w_self [o][i] hi
__device__ __align__(16) __nv_bfloat16 g_Wsl[D * D];         // w_self [o][i] lo
__device__ int g_counts[NREL];
__device__ int g_cursor[NREL];
__device__ int g_sorted[SORT_CAP];
__device__ int g_i32 = 0;   // sticky dtype flag: deterministic for fixed inputs

__device__ __forceinline__ int ld_idx(const void* p, size_t i, int is32) {
    return is32 ? ((const int*)p)[i] : (int)((const long long*)p)[i];
}
__device__ __forceinline__ void red4(float* p, float a, float b, float c, float d) {
    asm volatile("red.global.add.v4.f32 [%0], {%1,%2,%3,%4};"
                 :: "l"(p), "f"(a), "f"(b), "f"(c), "f"(d) : "memory");
}

// ================= fused init =================
__global__ void init_k(const void* __restrict__ etype,
                       const float* __restrict__ bases,
                       const float* __restrict__ coeff,
                       const float* __restrict__ wself, int E) {
    int i = blockIdx.x * blockDim.x + threadIdx.x;
    if (i < NREL) { g_counts[i] = 0; g_cursor[i] = 0; }
    if (i < SORT_CAP) g_sorted[i] = -1;
    if (i < 32768 && i < E / 2) {
        if (((const int*)etype)[2 * i + 1] != 0 && g_i32 == 0) atomicExch(&g_i32, 1);
    }
    if (i < NREL * D * D) {
        int r = i >> 14, o = (i >> 7) & 127, ii = i & 127;
        float acc = 0.f;
#pragma unroll
        for (int b = 0; b < NBASES; b++)
            acc += __ldg(&coeff[r * NBASES + b]) * __ldg(&bases[b * D * D + ii * D + o]);
        __nv_bfloat16 h = __float2bfloat16(acc);
        g_Wh[i] = h;
        g_Wl[i] = __float2bfloat16(acc - __bfloat162float(h));
    }
    if (i < D * D) {
        float w = wself[i];
        __nv_bfloat16 h = __float2bfloat16(w);
        g_Wsh[i] = h;
        g_Wsl[i] = __float2bfloat16(w - __bfloat162float(h));
    }
}

// ================= histogram (smem-aggregated) =================
__global__ void hist_k(const void* __restrict__ etype, int E) {
    __shared__ int h[NREL];
    int tid = threadIdx.x;
    if (tid < NREL) h[tid] = 0;
    __syncthreads();
    int i = blockIdx.x * blockDim.x + tid;
    int is32 = g_i32;
    if (i < E) {
        int t = ld_idx(etype, i, is32);
        if (t >= 0 && t < NREL) atomicAdd(&h[t], 1);
    }
    __syncthreads();
    if (tid < NREL && h[tid] > 0) atomicAdd(&g_counts[tid], h[tid]);
}

// ================= scatter (scan fused per block) =================
__global__ void scatter_k(const void* __restrict__ etype, int E) {
    __shared__ int cnt[NREL], base[NREL], soff[NREL];
    int tid = threadIdx.x;
    if (tid < NREL) cnt[tid] = 0;
    if (tid == 0) {
        int off = 0;
        for (int r = 0; r < NREL; r++) {
            soff[r] = off;
            off += ((g_counts[r] + TILE - 1) / TILE) * TILE;
        }
    }
    __syncthreads();
    int i = blockIdx.x * blockDim.x + tid;
    int is32 = g_i32;
    int t = -1, rank = 0;
    if (i < E) {
        t = ld_idx(etype, i, is32);
        if (t >= 0 && t < NREL) rank = atomicAdd(&cnt[t], 1);
        else t = -1;
    }
    __syncthreads();
    if (tid < NREL && cnt[tid] > 0) base[tid] = atomicAdd(&g_cursor[tid], cnt[tid]);
    __syncthreads();
    if (t >= 0) g_sorted[soff[t] + base[t] + rank] = i;
}

// ================= GEMM helpers =================
extern __shared__ char smem_raw[];

__device__ __forceinline__ void split_store(char* sm, int e, int lane, float4 v) {
    __nv_bfloat16 h0 = __float2bfloat16(v.x), h1 = __float2bfloat16(v.y);
    __nv_bfloat16 h2 = __float2bfloat16(v.z), h3 = __float2bfloat16(v.w);
    __nv_bfloat16 l0 = __float2bfloat16(v.x - __bfloat162float(h0));
    __nv_bfloat16 l1 = __float2bfloat16(v.y - __bfloat162float(h1));
    __nv_bfloat16 l2 = __float2bfloat16(v.z - __bfloat162float(h2));
    __nv_bfloat16 l3 = __float2bfloat16(v.w - __bfloat162float(h3));
    uint32_t hp0 = ((uint32_t)__bfloat16_as_ushort(h1) << 16) | __bfloat16_as_ushort(h0);
    uint32_t hp1 = ((uint32_t)__bfloat16_as_ushort(h3) << 16) | __bfloat16_as_ushort(h2);
    uint32_t lp0 = ((uint32_t)__bfloat16_as_ushort(l1) << 16) | __bfloat16_as_ushort(l0);
    uint32_t lp1 = ((uint32_t)__bfloat16_as_ushort(l3) << 16) | __bfloat16_as_ushort(l2);
    uint32_t off = (uint32_t)e * ROWB + (uint32_t)lane * 8;
    *(uint2*)(sm + XH_OFF + off) = make_uint2(hp0, hp1);
    *(uint2*)(sm + XL_OFF + off) = make_uint2(lp0, lp1);
}

__device__ __forceinline__ void load_w(char* sm, const __nv_bfloat16* Wh,
                                       const __nv_bfloat16* Wl, int tid) {
#pragma unroll
    for (int it = 0; it < 8; it++) {
        int c = it * 256 + tid;
        int o = c >> 4, k16 = (c & 15) * 16;
        *(uint4*)(sm + WH_OFF + o * ROWB + k16) = ((const uint4*)Wh)[c];
        *(uint4*)(sm + WL_OFF + o * ROWB + k16) = ((const uint4*)Wl)[c];
    }
}

// 3-product split-bf16 64x128x128 tile GEMM; result left in smem f32 (stride OLD)
__device__ __forceinline__ void mma_tile(char* sm, int warp) {
    const int wm = warp & 1, wn = warp >> 1;           // 2 x 4 warp grid, 32x32 each
    const __nv_bfloat16* Ah = (const __nv_bfloat16*)(sm + XH_OFF) + wm * 32 * LDA;
    const __nv_bfloat16* Al = (const __nv_bfloat16*)(sm + XL_OFF) + wm * 32 * LDA;
    const __nv_bfloat16* Bh = (const __nv_bfloat16*)(sm + WH_OFF) + wn * 32 * LDA;
    const __nv_bfloat16* Bl = (const __nv_bfloat16*)(sm + WL_OFF) + wn * 32 * LDA;

    wmma::fragment<wmma::accumulator, 16, 16, 16, float> acc[2][2];
#pragma unroll
    for (int i = 0; i < 2; i++)
#pragma unroll
        for (int j = 0; j < 2; j++) wmma::fill_fragment(acc[i][j], 0.f);

#pragma unroll
    for (int kk = 0; kk < 8; kk++) {
        const int k0 = kk * 16;
        wmma::fragment<wmma::matrix_a, 16, 16, 16, __nv_bfloat16, wmma::row_major> ah[2], al[2];
        wmma::fragment<wmma::matrix_b, 16, 16, 16, __nv_bfloat16, wmma::col_major> bh[2], bl[2];
#pragma unroll
        for (int i = 0; i < 2; i++) {
            wmma::load_matrix_sync(ah[i], Ah + i * 16 * LDA + k0, LDA);
            wmma::load_matrix_sync(al[i], Al + i * 16 * LDA + k0, LDA);
        }
#pragma unroll
        for (int j = 0; j < 2; j++) {
            wmma::load_matrix_sync(bh[j], Bh + j * 16 * LDA + k0, LDA);
            wmma::load_matrix_sync(bl[j], Bl + j * 16 * LDA + k0, LDA);
        }
#pragma unroll
        for (int i = 0; i < 2; i++)
#pragma unroll
            for (int j = 0; j < 2; j++) {
                wmma::mma_sync(acc[i][j], ah[i], bh[j], acc[i][j]);
                wmma::mma_sync(acc[i][j], ah[i], bl[j], acc[i][j]);
                wmma::mma_sync(acc[i][j], al[i], bh[j], acc[i][j]);
            }
    }

    __syncthreads();   // out tile aliases X region
    float* ot = (float*)sm;
#pragma unroll
    for (int i = 0; i < 2; i++)
#pragma unroll
        for (int j = 0; j < 2; j++)
            wmma::store_matrix_sync(ot + (wm * 32 + i * 16) * OLD + wn * 32 + j * 16,
                                    acc[i][j], OLD, wmma::mem_row_major);
}

// ================= unified GEMM: edge tiles + self-loop tiles =================
__global__ __launch_bounds__(256, 2)
void gemm_k(const float* __restrict__ x,
            const void* __restrict__ eidx,
            const void* __restrict__ etype,
            float* __restrict__ out, int E, int N, int nEdgeTiles) {
    __shared__ int srow[TILE], scol[TILE], s_rel;
    char* sm = smem_raw;
    const int tid = threadIdx.x;
    const int is32 = g_i32;
    const bool isEdge = (int)blockIdx.x < nEdgeTiles;

    if (isEdge) {
        const int base = blockIdx.x * TILE;
        if (tid == 0) {
            int id0 = g_sorted[base];
            s_rel = (id0 >= 0) ? ld_idx(etype, id0, is32) : -1;
        }
        if (tid < TILE) {
            int id = g_sorted[base + tid];
            int r = -1, c = 0;
            if (id >= 0) {
                r = ld_idx(eidx, id, is32);
                c = ld_idx(eidx, (size_t)E + id, is32);
                if ((unsigned)r >= (unsigned)N) r = -1;
                if ((unsigned)c >= (unsigned)N) c = 0;
            }
            srow[tid] = r; scol[tid] = c;
        }
    } else {
        const int n0 = ((int)blockIdx.x - nEdgeTiles) * TILE;
        if (tid == 0) s_rel = NREL;               // marker: self-loop
        if (tid < TILE) {
            int n = n0 + tid;
            srow[tid] = (n < N) ? n : -1;
            scol[tid] = (n < N) ? n : 0;
        }
    }
    __syncthreads();
    const int rel = s_rel;
    if (rel < 0) return;                          // fully padded edge tile

    if (rel < NREL)
        load_w(sm, g_Wh + (size_t)rel * D * D, g_Wl + (size_t)rel * D * D, tid);
    else
        load_w(sm, g_Wsh, g_Wsl, tid);

    const int warp = tid >> 5, lane = tid & 31;
#pragma unroll
    for (int j = 0; j < 8; j++) {
        int e = warp * 8 + j;
        float4 v = ((const float4*)(x + (size_t)scol[e] * D))[lane];
        split_store(sm, e, lane, v);
    }
    __syncthreads();

    mma_tile(sm, warp);
    __syncthreads();

    // scatter-add: thread -> (row, 32-col chunk); 256 = 64 rows x 4 chunks
    {
        const float* ot = (const float*)sm;
        const int e = tid >> 2;
        const int c0 = (tid & 3) * 32;
        const int r = srow[e];
        if (r >= 0) {
            const float* src = ot + e * OLD + c0;
            float* dst = out + (size_t)r * D + c0;
#pragma unroll
            for (int g = 0; g < 8; g++)
                red4(dst + g * 4, src[g * 4], src[g * 4 + 1], src[g * 4 + 2], src[g * 4 + 3]);
        }
    }
}

// ================= host launcher =================
extern "C" void kernel_launch(void* const* d_in, const int* in_sizes, int n_in,
                              void* d_out, int out_size) {
    const float* x     = (const float*)d_in[0];
    const void*  eidx  = d_in[1];
    const void*  etype = d_in[2];
    const float* bases = (const float*)d_in[3];
    const float* coeff = (const float*)d_in[4];
    const float* wself = (const float*)d_in[5];
    float* out = (float*)d_out;

    const int N = in_sizes[0] / D;
    const int E = in_sizes[2];
    const int nSelfTiles = (N + TILE - 1) / TILE;

    cudaFuncSetAttribute(gemm_k, cudaFuncAttributeMaxDynamicSharedMemorySize, GEMM_SMEM);
    // load-bearing: without full carveout the driver picks the 132KB tier -> 1 CTA/SM
    cudaFuncSetAttribute(gemm_k, cudaFuncAttributePreferredSharedMemoryCarveout, 100);

    cudaMemsetAsync(out, 0, (size_t)out_size * sizeof(float));
    init_k<<<(SORT_CAP + 255) / 256, 256>>>(etype, bases, coeff, wself, E);
    hist_k<<<(E + 255) / 256, 256>>>(etype, E);
    scatter_k<<<(E + 255) / 256, 256>>>(etype, E);
    gemm_k<<<NTILES + nSelfTiles, 256, GEMM_SMEM>>>(x, eidx, etype, out, E, N, NTILES);
}

// round 8
// speedup vs baseline: 1.6581x; 1.6581x over previous
#include <cuda_runtime.h>
#include <cuda_fp16.h>
#include <mma.h>
#include <cstdint>
#include <cstring>

using namespace nvcuda;

#define D        128
#define NREL     16
#define NBASES   8
#define TILE     64                                // rows per tile
#define MAXE     600000
#define NTILES   ((MAXE / TILE) + NREL + 2)        // 9393 edge-tile capacity
#define SORT_CAP (NTILES * TILE)                   // 601152

// ---- smem layout (fp16 tiles, row stride 136 elems = 272B) ----
#define LDA      136
#define ROWB     (LDA * 2)          // 272 bytes per row
#define XTILE_B  (TILE * ROWB)      // 17408 (64-row X tile)
#define WTILE_B  (D * ROWB)         // 34816 (128-row W tile)
#define X_OFF    0
#define W_OFF    XTILE_B
#define GEMM_SMEM (XTILE_B + WTILE_B)              // 52224 -> 4 CTAs/SM
#define OLD      132                // f32 out-tile stride; 64*132*4=33792 <= GEMM_SMEM

// -------- device scratch --------
__device__ __align__(16) __half g_W[NREL * D * D];   // [r][o][i] fp16
__device__ __align__(16) __half g_Ws[D * D];         // w_self [o][i] fp16
__device__ int g_counts[NREL];
__device__ int g_cursor[NREL];
__device__ int g_sorted[SORT_CAP];
__device__ int g_i32 = 0;   // sticky dtype flag: deterministic for fixed inputs

__device__ __forceinline__ int ld_idx(const void* p, size_t i, int is32) {
    return is32 ? ((const int*)p)[i] : (int)((const long long*)p)[i];
}
__device__ __forceinline__ void red4(float* p, float a, float b, float c, float d) {
    asm volatile("red.global.add.v4.f32 [%0], {%1,%2,%3,%4};"
                 :: "l"(p), "f"(a), "f"(b), "f"(c), "f"(d) : "memory");
}

// ================= fused init =================
__global__ void init_k(const void* __restrict__ etype,
                       const float* __restrict__ bases,
                       const float* __restrict__ coeff,
                       const float* __restrict__ wself, int E) {
    int i = blockIdx.x * blockDim.x + threadIdx.x;
    if (i < NREL) { g_counts[i] = 0; g_cursor[i] = 0; }
    if (i < SORT_CAP) g_sorted[i] = -1;
    if (i < 32768 && i < E / 2) {
        if (((const int*)etype)[2 * i + 1] != 0 && g_i32 == 0) atomicExch(&g_i32, 1);
    }
    if (i < NREL * D * D) {
        int r = i >> 14, o = (i >> 7) & 127, ii = i & 127;
        float acc = 0.f;
#pragma unroll
        for (int b = 0; b < NBASES; b++)
            acc += __ldg(&coeff[r * NBASES + b]) * __ldg(&bases[b * D * D + ii * D + o]);
        g_W[i] = __float2half_rn(acc);
    }
    if (i < D * D) g_Ws[i] = __float2half_rn(wself[i]);   // already [o][i]
}

// ================= histogram (smem-aggregated) =================
__global__ void hist_k(const void* __restrict__ etype, int E) {
    __shared__ int h[NREL];
    int tid = threadIdx.x;
    if (tid < NREL) h[tid] = 0;
    __syncthreads();
    int i = blockIdx.x * blockDim.x + tid;
    int is32 = g_i32;
    if (i < E) {
        int t = ld_idx(etype, i, is32);
        if (t >= 0 && t < NREL) atomicAdd(&h[t], 1);
    }
    __syncthreads();
    if (tid < NREL && h[tid] > 0) atomicAdd(&g_counts[tid], h[tid]);
}

// ================= scatter (scan fused per block) =================
__global__ void scatter_k(const void* __restrict__ etype, int E) {
    __shared__ int cnt[NREL], base[NREL], soff[NREL];
    int tid = threadIdx.x;
    if (tid < NREL) cnt[tid] = 0;
    if (tid == 0) {
        int off = 0;
        for (int r = 0; r < NREL; r++) {
            soff[r] = off;
            off += ((g_counts[r] + TILE - 1) / TILE) * TILE;
        }
    }
    __syncthreads();
    int i = blockIdx.x * blockDim.x + tid;
    int is32 = g_i32;
    int t = -1, rank = 0;
    if (i < E) {
        t = ld_idx(etype, i, is32);
        if (t >= 0 && t < NREL) rank = atomicAdd(&cnt[t], 1);
        else t = -1;
    }
    __syncthreads();
    if (tid < NREL && cnt[tid] > 0) base[tid] = atomicAdd(&g_cursor[tid], cnt[tid]);
    __syncthreads();
    if (t >= 0) g_sorted[soff[t] + base[t] + rank] = i;
}

// ================= GEMM helpers =================
extern __shared__ char smem_raw[];

__device__ __forceinline__ void cvt_store(char* sm, int e, int lane, float4 v) {
    __half2 p0 = __floats2half2_rn(v.x, v.y);
    __half2 p1 = __floats2half2_rn(v.z, v.w);
    uint32_t u0, u1;
    memcpy(&u0, &p0, 4); memcpy(&u1, &p1, 4);
    uint32_t off = (uint32_t)e * ROWB + (uint32_t)lane * 8;
    *(uint2*)(sm + X_OFF + off) = make_uint2(u0, u1);
}

// load W tile from global [o][i] fp16 (2048 16B chunks), 256 threads
__device__ __forceinline__ void load_w(char* sm, const __half* W, int tid) {
#pragma unroll
    for (int it = 0; it < 8; it++) {
        int c = it * 256 + tid;
        int o = c >> 4, k16 = (c & 15) * 16;
        *(uint4*)(sm + W_OFF + o * ROWB + k16) = ((const uint4*)W)[c];
    }
}

// single-product fp16 64x128x128 tile GEMM; result left in smem f32 (stride OLD)
__device__ __forceinline__ void mma_tile(char* sm, int warp) {
    const int wm = warp & 1, wn = warp >> 1;           // 2x4 warp grid, 32x32 each
    const __half* A = (const __half*)(sm + X_OFF) + wm * 32 * LDA;
    const __half* B = (const __half*)(sm + W_OFF) + wn * 32 * LDA;

    wmma::fragment<wmma::accumulator, 16, 16, 16, float> acc[2][2];
#pragma unroll
    for (int i = 0; i < 2; i++)
#pragma unroll
        for (int j = 0; j < 2; j++) wmma::fill_fragment(acc[i][j], 0.f);

#pragma unroll
    for (int kk = 0; kk < 8; kk++) {
        const int k0 = kk * 16;
        wmma::fragment<wmma::matrix_a, 16, 16, 16, __half, wmma::row_major> a[2];
        wmma::fragment<wmma::matrix_b, 16, 16, 16, __half, wmma::col_major> b[2];
#pragma unroll
        for (int i = 0; i < 2; i++)
            wmma::load_matrix_sync(a[i], A + i * 16 * LDA + k0, LDA);
#pragma unroll
        for (int j = 0; j < 2; j++)
            wmma::load_matrix_sync(b[j], B + j * 16 * LDA + k0, LDA);
#pragma unroll
        for (int i = 0; i < 2; i++)
#pragma unroll
            for (int j = 0; j < 2; j++)
                wmma::mma_sync(acc[i][j], a[i], b[j], acc[i][j]);
    }

    __syncthreads();   // out tile aliases X+W region: all fragment reads done
    float* ot = (float*)sm;
#pragma unroll
    for (int i = 0; i < 2; i++)
#pragma unroll
        for (int j = 0; j < 2; j++)
            wmma::store_matrix_sync(ot + (wm * 32 + i * 16) * OLD + wn * 32 + j * 16,
                                    acc[i][j], OLD, wmma::mem_row_major);
}

// ================= unified GEMM: edge tiles + self-loop tiles =================
__global__ __launch_bounds__(256, 4)
void gemm_k(const float* __restrict__ x,
            const void* __restrict__ eidx,
            const void* __restrict__ etype,
            float* __restrict__ out, int E, int N, int nEdgeTiles) {
    __shared__ int srow[TILE], scol[TILE], s_rel;
    char* sm = smem_raw;
    const int tid = threadIdx.x;
    const int is32 = g_i32;
    const bool isEdge = (int)blockIdx.x < nEdgeTiles;

    if (isEdge) {
        const int base = blockIdx.x * TILE;
        if (tid == 0) {
            int id0 = g_sorted[base];
            s_rel = (id0 >= 0) ? ld_idx(etype, id0, is32) : -1;
        }
        if (tid < TILE) {
            int id = g_sorted[base + tid];
            int r = -1, c = 0;
            if (id >= 0) {
                r = ld_idx(eidx, id, is32);
                c = ld_idx(eidx, (size_t)E + id, is32);
                if ((unsigned)r >= (unsigned)N) r = -1;
                if ((unsigned)c >= (unsigned)N) c = 0;
            }
            srow[tid] = r; scol[tid] = c;
        }
    } else {
        const int n0 = ((int)blockIdx.x - nEdgeTiles) * TILE;
        if (tid == 0) s_rel = NREL;               // marker: self-loop
        if (tid < TILE) {
            int n = n0 + tid;
            srow[tid] = (n < N) ? n : -1;
            scol[tid] = (n < N) ? n : 0;
        }
    }
    __syncthreads();
    const int rel = s_rel;
    if (rel < 0) return;                          // fully padded edge tile

    load_w(sm, (rel < NREL) ? (g_W + (size_t)rel * D * D) : g_Ws, tid);

    const int warp = tid >> 5, lane = tid & 31;
#pragma unroll
    for (int j = 0; j < 8; j++) {
        int e = warp * 8 + j;
        float4 v = ((const float4*)(x + (size_t)scol[e] * D))[lane];
        cvt_store(sm, e, lane, v);
    }
    __syncthreads();

    mma_tile(sm, warp);
    __syncthreads();

    // scatter-add: thread -> (row, 32-col chunk); 256 = 64 rows x 4 chunks
    {
        const float* ot = (const float*)sm;
        const int e = tid >> 2;
        const int c0 = (tid & 3) * 32;
        const int r = srow[e];
        if (r >= 0) {
            const float* src = ot + e * OLD + c0;
            float* dst = out + (size_t)r * D + c0;
#pragma unroll
            for (int g = 0; g < 8; g++)
                red4(dst + g * 4, src[g * 4], src[g * 4 + 1], src[g * 4 + 2], src[g * 4 + 3]);
        }
    }
}

// ================= host launcher =================
extern "C" void kernel_launch(void* const* d_in, const int* in_sizes, int n_in,
                              void* d_out, int out_size) {
    const float* x     = (const float*)d_in[0];
    const void*  eidx  = d_in[1];
    const void*  etype = d_in[2];
    const float* bases = (const float*)d_in[3];
    const float* coeff = (const float*)d_in[4];
    const float* wself = (const float*)d_in[5];
    float* out = (float*)d_out;

    const int N = in_sizes[0] / D;
    const int E = in_sizes[2];
    const int nSelfTiles = (N + TILE - 1) / TILE;

    cudaFuncSetAttribute(gemm_k, cudaFuncAttributeMaxDynamicSharedMemorySize, GEMM_SMEM);
    cudaFuncSetAttribute(gemm_k, cudaFuncAttributePreferredSharedMemoryCarveout, 100);

    cudaMemsetAsync(out, 0, (size_t)out_size * sizeof(float));
    init_k<<<(SORT_CAP + 255) / 256, 256>>>(etype, bases, coeff, wself, E);
    hist_k<<<(E + 255) / 256, 256>>>(etype, E);
    scatter_k<<<(E + 255) / 256, 256>>>(etype, E);
    gemm_k<<<NTILES + nSelfTiles, 256, GEMM_SMEM>>>(x, eidx, etype, out, E, N, NTILES);
}

// round 9
// speedup vs baseline: 2.1681x; 1.3076x over previous
#include <cuda_runtime.h>
#include <cuda_fp16.h>
#include <cstdint>
#include <cstring>

#define D        128
#define NREL     16
#define NBASES   8
#define TILE     64                                // rows per tile
#define MAXE     600000
#define NTILES   ((MAXE / TILE) + NREL + 2)        // 9393 edge-tile capacity
#define SORT_CAP (NTILES * TILE)                   // 601152

// ---- smem layout (fp16 tiles, row stride 136 elems = 272B) ----
#define LDA      136
#define ROWB     (LDA * 2)          // 272 bytes per row
#define XTILE_B  (TILE * ROWB)      // 17408 (64-row X tile)
#define WTILE_B  (D * ROWB)         // 34816 (128-row W tile)
#define X_OFF    0
#define W_OFF    XTILE_B
#define GEMM_SMEM (XTILE_B + WTILE_B)              // 52224 -> 4 CTAs/SM

// -------- device scratch --------
__device__ __align__(16) __half g_W[NREL * D * D];   // [r][o][i] fp16
__device__ __align__(16) __half g_Ws[D * D];         // w_self [o][i] fp16
__device__ int g_counts[NREL];
__device__ int g_cursor[NREL];
__device__ int g_sorted[SORT_CAP];
__device__ int g_i32 = 0;   // sticky dtype flag: deterministic for fixed inputs

__device__ __forceinline__ int ld_idx(const void* p, size_t i, int is32) {
    return is32 ? ((const int*)p)[i] : (int)((const long long*)p)[i];
}
__device__ __forceinline__ void red2(float* p, float a, float b) {
    asm volatile("red.global.add.v2.f32 [%0], {%1,%2};"
                 :: "l"(p), "f"(a), "f"(b) : "memory");
}
__device__ __forceinline__ uint32_t smem_u32(const void* p) {
    uint32_t a;
    asm("{ .reg .u64 t; cvta.to.shared.u64 t, %1; cvt.u32.u64 %0, t; }" : "=r"(a) : "l"(p));
    return a;
}
__device__ __forceinline__ void ldsm4(uint32_t* r, uint32_t addr) {
    asm volatile("ldmatrix.sync.aligned.m8n8.x4.shared.b16 {%0,%1,%2,%3}, [%4];"
                 : "=r"(r[0]), "=r"(r[1]), "=r"(r[2]), "=r"(r[3]) : "r"(addr));
}
__device__ __forceinline__ void mma16816(float* c, const uint32_t* a,
                                         uint32_t b0, uint32_t b1) {
    asm volatile(
        "mma.sync.aligned.m16n8k16.row.col.f32.f16.f16.f32 "
        "{%0,%1,%2,%3}, {%4,%5,%6,%7}, {%8,%9}, {%0,%1,%2,%3};"
        : "+f"(c[0]), "+f"(c[1]), "+f"(c[2]), "+f"(c[3])
        : "r"(a[0]), "r"(a[1]), "r"(a[2]), "r"(a[3]), "r"(b0), "r"(b1));
}

// ================= fused init =================
__global__ void init_k(const void* __restrict__ etype,
                       const float* __restrict__ bases,
                       const float* __restrict__ coeff,
                       const float* __restrict__ wself, int E) {
    int i = blockIdx.x * blockDim.x + threadIdx.x;
    if (i < NREL) { g_counts[i] = 0; g_cursor[i] = 0; }
    if (i < SORT_CAP) g_sorted[i] = -1;
    if (i < 32768 && i < E / 2) {
        if (((const int*)etype)[2 * i + 1] != 0 && g_i32 == 0) atomicExch(&g_i32, 1);
    }
    if (i < NREL * D * D) {
        int r = i >> 14, o = (i >> 7) & 127, ii = i & 127;
        float acc = 0.f;
#pragma unroll
        for (int b = 0; b < NBASES; b++)
            acc += __ldg(&coeff[r * NBASES + b]) * __ldg(&bases[b * D * D + ii * D + o]);
        g_W[i] = __float2half_rn(acc);
    }
    if (i < D * D) g_Ws[i] = __float2half_rn(wself[i]);   // already [o][i]
}

// ================= histogram (smem-aggregated) =================
__global__ void hist_k(const void* __restrict__ etype, int E) {
    __shared__ int h[NREL];
    int tid = threadIdx.x;
    if (tid < NREL) h[tid] = 0;
    __syncthreads();
    int i = blockIdx.x * blockDim.x + tid;
    int is32 = g_i32;
    if (i < E) {
        int t = ld_idx(etype, i, is32);
        if (t >= 0 && t < NREL) atomicAdd(&h[t], 1);
    }
    __syncthreads();
    if (tid < NREL && h[tid] > 0) atomicAdd(&g_counts[tid], h[tid]);
}

// ================= scatter (scan fused per block) =================
__global__ void scatter_k(const void* __restrict__ etype, int E) {
    __shared__ int cnt[NREL], base[NREL], soff[NREL];
    int tid = threadIdx.x;
    if (tid < NREL) cnt[tid] = 0;
    if (tid == 0) {
        int off = 0;
        for (int r = 0; r < NREL; r++) {
            soff[r] = off;
            off += ((g_counts[r] + TILE - 1) / TILE) * TILE;
        }
    }
    __syncthreads();
    int i = blockIdx.x * blockDim.x + tid;
    int is32 = g_i32;
    int t = -1, rank = 0;
    if (i < E) {
        t = ld_idx(etype, i, is32);
        if (t >= 0 && t < NREL) rank = atomicAdd(&cnt[t], 1);
        else t = -1;
    }
    __syncthreads();
    if (tid < NREL && cnt[tid] > 0) base[tid] = atomicAdd(&g_cursor[tid], cnt[tid]);
    __syncthreads();
    if (t >= 0) g_sorted[soff[t] + base[t] + rank] = i;
}

// ================= GEMM helpers =================
extern __shared__ char smem_raw[];

__device__ __forceinline__ void cvt_store(char* sm, int e, int lane, float4 v) {
    __half2 p0 = __floats2half2_rn(v.x, v.y);
    __half2 p1 = __floats2half2_rn(v.z, v.w);
    uint32_t u0, u1;
    memcpy(&u0, &p0, 4); memcpy(&u1, &p1, 4);
    uint32_t off = (uint32_t)e * ROWB + (uint32_t)lane * 8;
    *(uint2*)(sm + X_OFF + off) = make_uint2(u0, u1);
}

// load W tile from global [o][i] fp16 (2048 16B chunks), 256 threads
__device__ __forceinline__ void load_w(char* sm, const __half* W, int tid) {
#pragma unroll
    for (int it = 0; it < 8; it++) {
        int c = it * 256 + tid;
        int o = c >> 4, k16 = (c & 15) * 16;
        *(uint4*)(sm + W_OFF + o * ROWB + k16) = ((const uint4*)W)[c];
    }
}

// ================= unified GEMM: edge tiles + self-loop tiles =================
__global__ __launch_bounds__(256, 4)
void gemm_k(const float* __restrict__ x,
            const void* __restrict__ eidx,
            const void* __restrict__ etype,
            float* __restrict__ out, int E, int N, int nEdgeTiles) {
    __shared__ int srow[TILE], scol[TILE], s_rel;
    char* sm = smem_raw;
    const int tid = threadIdx.x;
    const int is32 = g_i32;
    const bool isEdge = (int)blockIdx.x < nEdgeTiles;

    if (isEdge) {
        const int base = blockIdx.x * TILE;
        if (tid == 0) {
            int id0 = g_sorted[base];
            s_rel = (id0 >= 0) ? ld_idx(etype, id0, is32) : -1;
        }
        if (tid < TILE) {
            int id = g_sorted[base + tid];
            int r = -1, c = 0;
            if (id >= 0) {
                r = ld_idx(eidx, id, is32);
                c = ld_idx(eidx, (size_t)E + id, is32);
                if ((unsigned)r >= (unsigned)N) r = -1;
                if ((unsigned)c >= (unsigned)N) c = 0;
            }
            srow[tid] = r; scol[tid] = c;
        }
    } else {
        const int n0 = ((int)blockIdx.x - nEdgeTiles) * TILE;
        if (tid == 0) s_rel = NREL;               // marker: self-loop
        if (tid < TILE) {
            int n = n0 + tid;
            srow[tid] = (n < N) ? n : -1;
            scol[tid] = (n < N) ? n : 0;
        }
    }
    __syncthreads();
    const int rel = s_rel;
    if (rel < 0) return;                          // fully padded edge tile

    load_w(sm, (rel < NREL) ? (g_W + (size_t)rel * D * D) : g_Ws, tid);

    const int warp = tid >> 5, lane = tid & 31;
#pragma unroll
    for (int j = 0; j < 8; j++) {
        int e = warp * 8 + j;
        float4 v = ((const float4*)(x + (size_t)scol[e] * D))[lane];
        cvt_store(sm, e, lane, v);
    }
    __syncthreads();

    // ---- mma.sync mainloop: warp tile 32(m) x 32(n), 2x4 warp grid ----
    const int wm = warp & 1, wn = warp >> 1;
    const int g = lane >> 2, t = lane & 3;
    // ldmatrix lane->address maps
    const int ar = (lane & 7) + ((lane >> 3) & 1) * 8;   // A: row within 16
    const int ac = (lane >> 4) * 8;                      // A: col within 16
    const int bn = (lane >> 4) * 8 + (lane & 7);         // B: n-row within 16
    const int bk = ((lane >> 3) & 1) * 8;                // B: k-col within 16

    const uint32_t xb = smem_u32(sm + X_OFF) + (uint32_t)((wm * 32 + ar) * ROWB + ac * 2);
    const uint32_t wb = smem_u32(sm + W_OFF) + (uint32_t)((wn * 32 + bn) * ROWB + bk * 2);

    float acc[2][4][4];
#pragma unroll
    for (int mt = 0; mt < 2; mt++)
#pragma unroll
        for (int nt = 0; nt < 4; nt++)
#pragma unroll
            for (int q = 0; q < 4; q++) acc[mt][nt][q] = 0.f;

#pragma unroll
    for (int kk = 0; kk < 8; kk++) {
        const uint32_t koff = (uint32_t)(kk * 16 * 2);
        uint32_t a[2][4], b[2][4];
#pragma unroll
        for (int mt = 0; mt < 2; mt++)
            ldsm4(a[mt], xb + (uint32_t)(mt * 16 * ROWB) + koff);
#pragma unroll
        for (int n2 = 0; n2 < 2; n2++)
            ldsm4(b[n2], wb + (uint32_t)(n2 * 16 * ROWB) + koff);
#pragma unroll
        for (int mt = 0; mt < 2; mt++)
#pragma unroll
            for (int nt = 0; nt < 4; nt++)
                mma16816(acc[mt][nt], a[mt], b[nt >> 1][(nt & 1) * 2],
                         b[nt >> 1][(nt & 1) * 2 + 1]);
    }

    // ---- epilogue: red.global.add.v2 straight from accumulators ----
#pragma unroll
    for (int mt = 0; mt < 2; mt++) {
        const int m0 = wm * 32 + mt * 16 + g;
        const int r0 = srow[m0], r1 = srow[m0 + 8];
#pragma unroll
        for (int nt = 0; nt < 4; nt++) {
            const int col = wn * 32 + nt * 8 + 2 * t;
            if (r0 >= 0) red2(out + (size_t)r0 * D + col, acc[mt][nt][0], acc[mt][nt][1]);
            if (r1 >= 0) red2(out + (size_t)r1 * D + col, acc[mt][nt][2], acc[mt][nt][3]);
        }
    }
}

// ================= host launcher =================
extern "C" void kernel_launch(void* const* d_in, const int* in_sizes, int n_in,
                              void* d_out, int out_size) {
    const float* x     = (const float*)d_in[0];
    const void*  eidx  = d_in[1];
    const void*  etype = d_in[2];
    const float* bases = (const float*)d_in[3];
    const float* coeff = (const float*)d_in[4];
    const float* wself = (const float*)d_in[5];
    float* out = (float*)d_out;

    const int N = in_sizes[0] / D;
    const int E = in_sizes[2];
    const int nSelfTiles = (N + TILE - 1) / TILE;

    cudaFuncSetAttribute(gemm_k, cudaFuncAttributeMaxDynamicSharedMemorySize, GEMM_SMEM);
    cudaFuncSetAttribute(gemm_k, cudaFuncAttributePreferredSharedMemoryCarveout, 100);

    cudaMemsetAsync(out, 0, (size_t)out_size * sizeof(float));
    init_k<<<(SORT_CAP + 255) / 256, 256>>>(etype, bases, coeff, wself, E);
    hist_k<<<(E + 255) / 256, 256>>>(etype, E);
    scatter_k<<<(E + 255) / 256, 256>>>(etype, E);
    gemm_k<<<NTILES + nSelfTiles, 256, GEMM_SMEM>>>(x, eidx, etype, out, E, N, NTILES);
}

// round 10
// speedup vs baseline: 2.6030x; 1.2006x over previous
#include <cuda_runtime.h>
#include <cuda_fp16.h>
#include <cstdint>
#include <cstring>

#define D        128
#define NREL     16
#define NBASES   8
#define TILE     64                                // rows per tile
#define CHUNK    4                                 // tiles per CTA
#define MAXE     600000
#define NTILES   ((MAXE / TILE) + NREL + 2)        // 9393 edge-tile capacity
#define SORT_CAP (NTILES * TILE)                   // 601152

// ---- smem layout (fp16 tiles, row stride 136 elems = 272B) ----
#define LDA      136
#define ROWB     (LDA * 2)          // 272 bytes per row
#define XTILE_B  (TILE * ROWB)      // 17408 (64-row X tile)
#define WTILE_B  (D * ROWB)         // 34816 (128-row W tile)
#define X_OFF    0
#define W_OFF    XTILE_B
#define GEMM_SMEM (XTILE_B + WTILE_B)              // 52224 -> 4 CTAs/SM

// -------- device scratch --------
__device__ __align__(16) __half g_W[NREL * D * D];   // [r][o][i] fp16
__device__ __align__(16) __half g_Ws[D * D];         // w_self [o][i] fp16
__device__ int g_counts[NREL];
__device__ int g_cursor[NREL];
__device__ int g_sorted[SORT_CAP];
__device__ int g_i32 = 0;   // sticky dtype flag: deterministic for fixed inputs

__device__ __forceinline__ int ld_idx(const void* p, size_t i, int is32) {
    return is32 ? ((const int*)p)[i] : (int)((const long long*)p)[i];
}
__device__ __forceinline__ void red2(float* p, float a, float b) {
    asm volatile("red.global.add.v2.f32 [%0], {%1,%2};"
                 :: "l"(p), "f"(a), "f"(b) : "memory");
}
__device__ __forceinline__ uint32_t smem_u32(const void* p) {
    uint32_t a;
    asm("{ .reg .u64 t; cvta.to.shared.u64 t, %1; cvt.u32.u64 %0, t; }" : "=r"(a) : "l"(p));
    return a;
}
__device__ __forceinline__ void ldsm4(uint32_t* r, uint32_t addr) {
    asm volatile("ldmatrix.sync.aligned.m8n8.x4.shared.b16 {%0,%1,%2,%3}, [%4];"
                 : "=r"(r[0]), "=r"(r[1]), "=r"(r[2]), "=r"(r[3]) : "r"(addr));
}
__device__ __forceinline__ void mma16816(float* c, const uint32_t* a,
                                         uint32_t b0, uint32_t b1) {
    asm volatile(
        "mma.sync.aligned.m16n8k16.row.col.f32.f16.f16.f32 "
        "{%0,%1,%2,%3}, {%4,%5,%6,%7}, {%8,%9}, {%0,%1,%2,%3};"
        : "+f"(c[0]), "+f"(c[1]), "+f"(c[2]), "+f"(c[3])
        : "r"(a[0]), "r"(a[1]), "r"(a[2]), "r"(a[3]), "r"(b0), "r"(b1));
}

// ================= fused init =================
__global__ void init_k(const void* __restrict__ etype,
                       const float* __restrict__ bases,
                       const float* __restrict__ coeff,
                       const float* __restrict__ wself, int E) {
    int i = blockIdx.x * blockDim.x + threadIdx.x;
    if (i < NREL) { g_counts[i] = 0; g_cursor[i] = 0; }
    if (i < SORT_CAP) g_sorted[i] = -1;
    if (i < 32768 && i < E / 2) {
        if (((const int*)etype)[2 * i + 1] != 0 && g_i32 == 0) atomicExch(&g_i32, 1);
    }
    if (i < NREL * D * D) {
        int r = i >> 14, o = (i >> 7) & 127, ii = i & 127;
        float acc = 0.f;
#pragma unroll
        for (int b = 0; b < NBASES; b++)
            acc += __ldg(&coeff[r * NBASES + b]) * __ldg(&bases[b * D * D + ii * D + o]);
        g_W[i] = __float2half_rn(acc);
    }
    if (i < D * D) g_Ws[i] = __float2half_rn(wself[i]);   // already [o][i]
}

// ================= histogram (smem-aggregated) =================
__global__ void hist_k(const void* __restrict__ etype, int E) {
    __shared__ int h[NREL];
    int tid = threadIdx.x;
    if (tid < NREL) h[tid] = 0;
    __syncthreads();
    int i = blockIdx.x * blockDim.x + tid;
    int is32 = g_i32;
    if (i < E) {
        int t = ld_idx(etype, i, is32);
        if (t >= 0 && t < NREL) atomicAdd(&h[t], 1);
    }
    __syncthreads();
    if (tid < NREL && h[tid] > 0) atomicAdd(&g_counts[tid], h[tid]);
}

// ================= scatter (scan fused per block) =================
__global__ void scatter_k(const void* __restrict__ etype, int E) {
    __shared__ int cnt[NREL], base[NREL], soff[NREL];
    int tid = threadIdx.x;
    if (tid < NREL) cnt[tid] = 0;
    if (tid == 0) {
        int off = 0;
        for (int r = 0; r < NREL; r++) {
            soff[r] = off;
            off += ((g_counts[r] + TILE - 1) / TILE) * TILE;
        }
    }
    __syncthreads();
    int i = blockIdx.x * blockDim.x + tid;
    int is32 = g_i32;
    int t = -1, rank = 0;
    if (i < E) {
        t = ld_idx(etype, i, is32);
        if (t >= 0 && t < NREL) rank = atomicAdd(&cnt[t], 1);
        else t = -1;
    }
    __syncthreads();
    if (tid < NREL && cnt[tid] > 0) base[tid] = atomicAdd(&g_cursor[tid], cnt[tid]);
    __syncthreads();
    if (t >= 0) g_sorted[soff[t] + base[t] + rank] = i;
}

// ================= GEMM helpers =================
extern __shared__ char smem_raw[];

__device__ __forceinline__ void cvt_store(char* sm, int e, int lane, float4 v) {
    __half2 p0 = __floats2half2_rn(v.x, v.y);
    __half2 p1 = __floats2half2_rn(v.z, v.w);
    uint32_t u0, u1;
    memcpy(&u0, &p0, 4); memcpy(&u1, &p1, 4);
    uint32_t off = (uint32_t)e * ROWB + (uint32_t)lane * 8;
    *(uint2*)(sm + X_OFF + off) = make_uint2(u0, u1);
}

// load W tile from global [o][i] fp16 (2048 16B chunks), 256 threads
__device__ __forceinline__ void load_w(char* sm, const __half* W, int tid) {
#pragma unroll
    for (int it = 0; it < 8; it++) {
        int c = it * 256 + tid;
        int o = c >> 4, k16 = (c & 15) * 16;
        *(uint4*)(sm + W_OFF + o * ROWB + k16) = ((const uint4*)W)[c];
    }
}

// ================= unified multi-tile GEMM =================
__global__ __launch_bounds__(256, 4)
void gemm_k(const float* __restrict__ x,
            const void* __restrict__ eidx,
            const void* __restrict__ etype,
            float* __restrict__ out, int E, int N, int nEdgeTiles, int nTotal) {
    __shared__ int srow[TILE];
    char* sm = smem_raw;
    const int tid = threadIdx.x;
    const int warp = tid >> 5, lane = tid & 31;
    const int is32 = g_i32;

    // mma / ldmatrix lane maps (loop-invariant)
    const int wm = warp & 1, wn = warp >> 1;
    const int gq = lane >> 2, t4 = lane & 3;
    const int ar = (lane & 7) + ((lane >> 3) & 1) * 8;
    const int ac = (lane >> 4) * 8;
    const int bn = (lane >> 4) * 8 + (lane & 7);
    const int bk = ((lane >> 3) & 1) * 8;
    const uint32_t xb = smem_u32(sm + X_OFF) + (uint32_t)((wm * 32 + ar) * ROWB + ac * 2);
    const uint32_t wb = smem_u32(sm + W_OFF) + (uint32_t)((wn * 32 + bn) * ROWB + bk * 2);

    int cur_rel = -2;
    const int tEnd = min((int)blockIdx.x * CHUNK + CHUNK, nTotal);

    for (int tIdx = (int)blockIdx.x * CHUNK; tIdx < tEnd; tIdx++) {
        const bool isEdge = tIdx < nEdgeTiles;
        int rel, loc;                          // loc: tile base (edge) or n0 (self)
        if (isEdge) {
            loc = tIdx * TILE;
            int id0 = g_sorted[loc];
            rel = (id0 >= 0) ? ld_idx(etype, id0, is32) : -1;
        } else {
            loc = (tIdx - nEdgeTiles) * TILE;
            rel = NREL;
        }

        if (rel >= 0) {
            if (rel != cur_rel) {             // W region free: post-mainloop sync of prev tile
                load_w(sm, (rel < NREL) ? (g_W + (size_t)rel * D * D) : g_Ws, tid);
                cur_rel = rel;
            }
            // per-warp index load (lane<8) + shfl broadcast; no idx sync needed
            int r = -1, c = 0;
            if (lane < 8) {
                int e = warp * 8 + lane;
                if (isEdge) {
                    int id = g_sorted[loc + e];
                    if (id >= 0) {
                        r = ld_idx(eidx, id, is32);
                        c = ld_idx(eidx, (size_t)E + id, is32);
                        if ((unsigned)r >= (unsigned)N) r = -1;
                        if ((unsigned)c >= (unsigned)N) c = 0;
                    }
                } else {
                    int n = loc + e;
                    r = (n < N) ? n : -1;
                    c = (n < N) ? n : 0;
                }
                srow[e] = r;
            }
#pragma unroll
            for (int j = 0; j < 8; j++) {
                int cj = __shfl_sync(0xffffffffu, c, j);
                float4 v = ((const float4*)(x + (size_t)cj * D))[lane];
                cvt_store(sm, warp * 8 + j, lane, v);
            }
        }
        __syncthreads();                       // X/W/srow visible

        if (rel >= 0) {
            float acc[2][4][4];
#pragma unroll
            for (int mt = 0; mt < 2; mt++)
#pragma unroll
                for (int nt = 0; nt < 4; nt++)
#pragma unroll
                    for (int q = 0; q < 4; q++) acc[mt][nt][q] = 0.f;

#pragma unroll
            for (int kk = 0; kk < 8; kk++) {
                const uint32_t koff = (uint32_t)(kk * 16 * 2);
                uint32_t a[2][4], b[2][4];
#pragma unroll
                for (int mt = 0; mt < 2; mt++)
                    ldsm4(a[mt], xb + (uint32_t)(mt * 16 * ROWB) + koff);
#pragma unroll
                for (int n2 = 0; n2 < 2; n2++)
                    ldsm4(b[n2], wb + (uint32_t)(n2 * 16 * ROWB) + koff);
#pragma unroll
                for (int mt = 0; mt < 2; mt++)
#pragma unroll
                    for (int nt = 0; nt < 4; nt++)
                        mma16816(acc[mt][nt], a[mt], b[nt >> 1][(nt & 1) * 2],
                                 b[nt >> 1][(nt & 1) * 2 + 1]);
            }

            // epilogue straight from accumulators
#pragma unroll
            for (int mt = 0; mt < 2; mt++) {
                const int m0 = wm * 32 + mt * 16 + gq;
                const int r0 = srow[m0], r1 = srow[m0 + 8];
#pragma unroll
                for (int nt = 0; nt < 4; nt++) {
                    const int col = wn * 32 + nt * 8 + 2 * t4;
                    if (r0 >= 0) red2(out + (size_t)r0 * D + col, acc[mt][nt][0], acc[mt][nt][1]);
                    if (r1 >= 0) red2(out + (size_t)r1 * D + col, acc[mt][nt][2], acc[mt][nt][3]);
                }
            }
        }
        __syncthreads();                       // protect X/W/srow for next tile
    }
}

// ================= host launcher =================
extern "C" void kernel_launch(void* const* d_in, const int* in_sizes, int n_in,
                              void* d_out, int out_size) {
    const float* x     = (const float*)d_in[0];
    const void*  eidx  = d_in[1];
    const void*  etype = d_in[2];
    const float* bases = (const float*)d_in[3];
    const float* coeff = (const float*)d_in[4];
    const float* wself = (const float*)d_in[5];
    float* out = (float*)d_out;

    const int N = in_sizes[0] / D;
    const int E = in_sizes[2];
    const int nSelfTiles = (N + TILE - 1) / TILE;
    const int nTotal = NTILES + nSelfTiles;
    const int nBlocks = (nTotal + CHUNK - 1) / CHUNK;

    cudaFuncSetAttribute(gemm_k, cudaFuncAttributeMaxDynamicSharedMemorySize, GEMM_SMEM);
    cudaFuncSetAttribute(gemm_k, cudaFuncAttributePreferredSharedMemoryCarveout, 100);

    cudaMemsetAsync(out, 0, (size_t)out_size * sizeof(float));
    init_k<<<(SORT_CAP + 255) / 256, 256>>>(etype, bases, coeff, wself, E);
    hist_k<<<(E + 255) / 256, 256>>>(etype, E);
    scatter_k<<<(E + 255) / 256, 256>>>(etype, E);
    gemm_k<<<nBlocks, 256, GEMM_SMEM>>>(x, eidx, etype, out, E, N, NTILES, nTotal);
}

// round 11
// speedup vs baseline: 2.6084x; 1.0021x over previous
#include <cuda_runtime.h>
#include <cuda_fp16.h>
#include <cstdint>
#include <cstring>

#define D        128
#define NREL     16
#define NBASES   8
#define TILE     64                                // rows per tile
#define CHUNK    4                                 // tiles per CTA
#define MAXE     600000
#define NTILES   ((MAXE / TILE) + NREL + 2)        // 9393 edge-tile capacity
#define SORT_CAP (NTILES * TILE)                   // 601152

// ---- smem layout (fp16 tiles, row stride 136 elems = 272B) ----
#define LDA      136
#define ROWB     (LDA * 2)          // 272 bytes per row
#define XTILE_B  (TILE * ROWB)      // 17408 (64-row X tile)
#define WTILE_B  (D * ROWB)         // 34816 (128-row W tile)
#define X_OFF    0
#define W_OFF    XTILE_B
#define GEMM_SMEM (XTILE_B + WTILE_B)              // 52224 -> 4 CTAs/SM

// -------- device scratch --------
__device__ __align__(16) __half g_W[NREL * D * D];   // [r][o][i] fp16
__device__ __align__(16) __half g_Ws[D * D];         // w_self [o][i] fp16
__device__ int g_counts[NREL];
__device__ int g_cursor[NREL];
__device__ int g_sorted[SORT_CAP];
__device__ int g_i32 = 0;   // sticky dtype flag: deterministic for fixed inputs

__device__ __forceinline__ int ld_idx(const void* p, size_t i, int is32) {
    return is32 ? ((const int*)p)[i] : (int)((const long long*)p)[i];
}
__device__ __forceinline__ void red2(float* p, float a, float b) {
    asm volatile("red.global.add.v2.f32 [%0], {%1,%2};"
                 :: "l"(p), "f"(a), "f"(b) : "memory");
}
__device__ __forceinline__ uint32_t smem_u32(const void* p) {
    uint32_t a;
    asm("{ .reg .u64 t; cvta.to.shared.u64 t, %1; cvt.u32.u64 %0, t; }" : "=r"(a) : "l"(p));
    return a;
}
__device__ __forceinline__ void ldsm4(uint32_t* r, uint32_t addr) {
    asm volatile("ldmatrix.sync.aligned.m8n8.x4.shared.b16 {%0,%1,%2,%3}, [%4];"
                 : "=r"(r[0]), "=r"(r[1]), "=r"(r[2]), "=r"(r[3]) : "r"(addr));
}
__device__ __forceinline__ void mma16816(float* c, const uint32_t* a,
                                         uint32_t b0, uint32_t b1) {
    asm volatile(
        "mma.sync.aligned.m16n8k16.row.col.f32.f16.f16.f32 "
        "{%0,%1,%2,%3}, {%4,%5,%6,%7}, {%8,%9}, {%0,%1,%2,%3};"
        : "+f"(c[0]), "+f"(c[1]), "+f"(c[2]), "+f"(c[3])
        : "r"(a[0]), "r"(a[1]), "r"(a[2]), "r"(a[3]), "r"(b0), "r"(b1));
}

// ================= fused init =================
__global__ void init_k(const void* __restrict__ etype,
                       const float* __restrict__ bases,
                       const float* __restrict__ coeff,
                       const float* __restrict__ wself, int E) {
    int i = blockIdx.x * blockDim.x + threadIdx.x;
    if (i < NREL) { g_counts[i] = 0; g_cursor[i] = 0; }
    if (i < SORT_CAP) g_sorted[i] = -1;
    if (i < 32768 && i < E / 2) {
        if (((const int*)etype)[2 * i + 1] != 0 && g_i32 == 0) atomicExch(&g_i32, 1);
    }
    if (i < NREL * D * D) {
        int r = i >> 14, o = (i >> 7) & 127, ii = i & 127;
        float acc = 0.f;
#pragma unroll
        for (int b = 0; b < NBASES; b++)
            acc += __ldg(&coeff[r * NBASES + b]) * __ldg(&bases[b * D * D + ii * D + o]);
        g_W[i] = __float2half_rn(acc);
    }
    if (i < D * D) g_Ws[i] = __float2half_rn(wself[i]);   // already [o][i]
}

// ================= histogram (smem-aggregated) =================
__global__ void hist_k(const void* __restrict__ etype, int E) {
    __shared__ int h[NREL];
    int tid = threadIdx.x;
    if (tid < NREL) h[tid] = 0;
    __syncthreads();
    int i = blockIdx.x * blockDim.x + tid;
    int is32 = g_i32;
    if (i < E) {
        int t = ld_idx(etype, i, is32);
        if (t >= 0 && t < NREL) atomicAdd(&h[t], 1);
    }
    __syncthreads();
    if (tid < NREL && h[tid] > 0) atomicAdd(&g_counts[tid], h[tid]);
}

// ================= scatter (scan fused per block) =================
__global__ void scatter_k(const void* __restrict__ etype, int E) {
    __shared__ int cnt[NREL], base[NREL], soff[NREL];
    int tid = threadIdx.x;
    if (tid < NREL) cnt[tid] = 0;
    if (tid == 0) {
        int off = 0;
        for (int r = 0; r < NREL; r++) {
            soff[r] = off;
            off += ((g_counts[r] + TILE - 1) / TILE) * TILE;
        }
    }
    __syncthreads();
    int i = blockIdx.x * blockDim.x + tid;
    int is32 = g_i32;
    int t = -1, rank = 0;
    if (i < E) {
        t = ld_idx(etype, i, is32);
        if (t >= 0 && t < NREL) rank = atomicAdd(&cnt[t], 1);
        else t = -1;
    }
    __syncthreads();
    if (tid < NREL && cnt[tid] > 0) base[tid] = atomicAdd(&g_cursor[tid], cnt[tid]);
    __syncthreads();
    if (t >= 0) g_sorted[soff[t] + base[t] + rank] = i;
}

// ================= GEMM helpers =================
extern __shared__ char smem_raw[];

__device__ __forceinline__ void cvt_store(char* sm, int e, int lane, float4 v) {
    __half2 p0 = __floats2half2_rn(v.x, v.y);
    __half2 p1 = __floats2half2_rn(v.z, v.w);
    uint32_t u0, u1;
    memcpy(&u0, &p0, 4); memcpy(&u1, &p1, 4);
    uint32_t off = (uint32_t)e * ROWB + (uint32_t)lane * 8;
    *(uint2*)(sm + X_OFF + off) = make_uint2(u0, u1);
}

// load W tile from global [o][i] fp16 (2048 16B chunks), 128 threads
__device__ __forceinline__ void load_w(char* sm, const __half* W, int tid) {
#pragma unroll
    for (int it = 0; it < 16; it++) {
        int c = it * 128 + tid;
        int o = c >> 4, k16 = (c & 15) * 16;
        *(uint4*)(sm + W_OFF + o * ROWB + k16) = ((const uint4*)W)[c];
    }
}

// ================= unified multi-tile GEMM (fat warps: 32x64 per warp) =================
__global__ __launch_bounds__(128, 4)
void gemm_k(const float* __restrict__ x,
            const void* __restrict__ eidx,
            const void* __restrict__ etype,
            float* __restrict__ out, int E, int N, int nEdgeTiles, int nTotal) {
    __shared__ int srow[TILE];
    char* sm = smem_raw;
    const int tid = threadIdx.x;
    const int warp = tid >> 5, lane = tid & 31;
    const int is32 = g_i32;

    // 2m x 2n warp grid; warp tile 32(m) x 64(n)
    const int wm = warp & 1, wn = warp >> 1;
    const int gq = lane >> 2, t4 = lane & 3;
    const int ar = (lane & 7) + ((lane >> 3) & 1) * 8;   // A ldmatrix row map
    const int ac = (lane >> 4) * 8;
    const int bn = (lane >> 4) * 8 + (lane & 7);         // B ldmatrix row map
    const int bk = ((lane >> 3) & 1) * 8;
    const uint32_t xb = smem_u32(sm + X_OFF) + (uint32_t)((wm * 32 + ar) * ROWB + ac * 2);
    const uint32_t wb = smem_u32(sm + W_OFF) + (uint32_t)((wn * 64 + bn) * ROWB + bk * 2);

    int cur_rel = -2;
    const int tEnd = min((int)blockIdx.x * CHUNK + CHUNK, nTotal);

    for (int tIdx = (int)blockIdx.x * CHUNK; tIdx < tEnd; tIdx++) {
        const bool isEdge = tIdx < nEdgeTiles;
        int rel, loc;
        if (isEdge) {
            loc = tIdx * TILE;
            int id0 = g_sorted[loc];
            rel = (id0 >= 0) ? ld_idx(etype, id0, is32) : -1;
        } else {
            loc = (tIdx - nEdgeTiles) * TILE;
            rel = NREL;
        }

        if (rel >= 0) {
            if (rel != cur_rel) {
                load_w(sm, (rel < NREL) ? (g_W + (size_t)rel * D * D) : g_Ws, tid);
                cur_rel = rel;
            }
            // per-warp index load (lane<16) + shfl broadcast; 16 rows per warp
            int r = -1, c = 0;
            if (lane < 16) {
                int e = warp * 16 + lane;
                if (isEdge) {
                    int id = g_sorted[loc + e];
                    if (id >= 0) {
                        r = ld_idx(eidx, id, is32);
                        c = ld_idx(eidx, (size_t)E + id, is32);
                        if ((unsigned)r >= (unsigned)N) r = -1;
                        if ((unsigned)c >= (unsigned)N) c = 0;
                    }
                } else {
                    int n = loc + e;
                    r = (n < N) ? n : -1;
                    c = (n < N) ? n : 0;
                }
                srow[e] = r;
            }
#pragma unroll
            for (int j = 0; j < 16; j++) {
                int cj = __shfl_sync(0xffffffffu, c, j);
                float4 v = ((const float4*)(x + (size_t)cj * D))[lane];
                cvt_store(sm, warp * 16 + j, lane, v);
            }
        }
        __syncthreads();                       // X/W/srow visible

        if (rel >= 0) {
            float acc[2][8][4];
#pragma unroll
            for (int mt = 0; mt < 2; mt++)
#pragma unroll
                for (int nt = 0; nt < 8; nt++)
#pragma unroll
                    for (int q = 0; q < 4; q++) acc[mt][nt][q] = 0.f;

#pragma unroll
            for (int kk = 0; kk < 8; kk++) {
                const uint32_t koff = (uint32_t)(kk * 16 * 2);
                uint32_t a[2][4], b[4][4];
#pragma unroll
                for (int mt = 0; mt < 2; mt++)
                    ldsm4(a[mt], xb + (uint32_t)(mt * 16 * ROWB) + koff);
#pragma unroll
                for (int n2 = 0; n2 < 4; n2++)
                    ldsm4(b[n2], wb + (uint32_t)(n2 * 16 * ROWB) + koff);
#pragma unroll
                for (int mt = 0; mt < 2; mt++)
#pragma unroll
                    for (int nt = 0; nt < 8; nt++)
                        mma16816(acc[mt][nt], a[mt], b[nt >> 1][(nt & 1) * 2],
                                 b[nt >> 1][(nt & 1) * 2 + 1]);
            }

            // epilogue straight from accumulators
#pragma unroll
            for (int mt = 0; mt < 2; mt++) {
                const int m0 = wm * 32 + mt * 16 + gq;
                const int r0 = srow[m0], r1 = srow[m0 + 8];
#pragma unroll
                for (int nt = 0; nt < 8; nt++) {
                    const int col = wn * 64 + nt * 8 + 2 * t4;
                    if (r0 >= 0) red2(out + (size_t)r0 * D + col, acc[mt][nt][0], acc[mt][nt][1]);
                    if (r1 >= 0) red2(out + (size_t)r1 * D + col, acc[mt][nt][2], acc[mt][nt][3]);
                }
            }
        }
        __syncthreads();                       // protect X/W/srow for next tile
    }
}

// ================= host launcher =================
extern "C" void kernel_launch(void* const* d_in, const int* in_sizes, int n_in,
                              void* d_out, int out_size) {
    const float* x     = (const float*)d_in[0];
    const void*  eidx  = d_in[1];
    const void*  etype = d_in[2];
    const float* bases = (const float*)d_in[3];
    const float* coeff = (const float*)d_in[4];
    const float* wself = (const float*)d_in[5];
    float* out = (float*)d_out;

    const int N = in_sizes[0] / D;
    const int E = in_sizes[2];
    const int nSelfTiles = (N + TILE - 1) / TILE;
    const int nTotal = NTILES + nSelfTiles;
    const int nBlocks = (nTotal + CHUNK - 1) / CHUNK;

    cudaFuncSetAttribute(gemm_k, cudaFuncAttributeMaxDynamicSharedMemorySize, GEMM_SMEM);
    cudaFuncSetAttribute(gemm_k, cudaFuncAttributePreferredSharedMemoryCarveout, 100);

    cudaMemsetAsync(out, 0, (size_t)out_size * sizeof(float));
    init_k<<<(SORT_CAP + 255) / 256, 256>>>(etype, bases, coeff, wself, E);
    hist_k<<<(E + 255) / 256, 256>>>(etype, E);
    scatter_k<<<(E + 255) / 256, 256>>>(etype, E);
    gemm_k<<<nBlocks, 128, GEMM_SMEM>>>(x, eidx, etype, out, E, N, NTILES, nTotal);
}